// round 11
// baseline (speedup 1.0000x reference)
#include <cuda_runtime.h>
#include <cuda_bf16.h>
#include <cuda_fp16.h>

#define BATCH 32
#define CDIM  512
#define LSIZE 32
#define NPIX  1024
#define HEADS 8
#define DH    64
#define OC    1536

// ---------------------------------------------------------------------------
// Device scratch. hi/lo bf16 pairs interleaved as uint2 (x=hi, y=lo).
// ---------------------------------------------------------------------------
__device__ float g_rp[CDIM * NPIX];
__device__ uint2 g_Whl[OC * 256];                 // [o][kp]      (kp = c/2)
__device__ uint2 g_Xhl[BATCH * 256 * NPIX];       // [b*256+kp][hw]
__device__ uint2 g_Qhl[BATCH * 256 * NPIX];       // [b*256+dp][hw]
__device__ uint2 g_Khl[BATCH * 256 * NPIX];       // K + rp
__device__ unsigned g_Vh[BATCH * CDIM * 512];     // fp16 key-pairs, kp-permuted

// ---------------------------------------------------------------------------
// helpers
// ---------------------------------------------------------------------------
__device__ __forceinline__ void split2(float x0, float x1, unsigned& h, unsigned& l) {
    __nv_bfloat16 h0 = __float2bfloat16(x0);
    __nv_bfloat16 h1 = __float2bfloat16(x1);
    __nv_bfloat16 l0 = __float2bfloat16(x0 - __bfloat162float(h0));
    __nv_bfloat16 l1 = __float2bfloat16(x1 - __bfloat162float(h1));
    h = ((unsigned)__bfloat16_as_ushort(h1) << 16) | __bfloat16_as_ushort(h0);
    l = ((unsigned)__bfloat16_as_ushort(l1) << 16) | __bfloat16_as_ushort(l0);
}
__device__ __forceinline__ unsigned packh2(float x0, float x1) {
    __half2 h = __floats2half2_rn(x0, x1);
    return *(unsigned*)&h;
}
__device__ __forceinline__ void mma16(float4& c, const unsigned* a, unsigned b0, unsigned b1) {
    asm volatile(
        "mma.sync.aligned.m16n8k16.row.col.f32.bf16.bf16.f32 "
        "{%0,%1,%2,%3}, {%4,%5,%6,%7}, {%8,%9}, {%0,%1,%2,%3};"
        : "+f"(c.x), "+f"(c.y), "+f"(c.z), "+f"(c.w)
        : "r"(a[0]), "r"(a[1]), "r"(a[2]), "r"(a[3]), "r"(b0), "r"(b1));
}
__device__ __forceinline__ void mma16f(float4& c, const unsigned* a, unsigned b0, unsigned b1) {
    asm volatile(
        "mma.sync.aligned.m16n8k16.row.col.f32.f16.f16.f32 "
        "{%0,%1,%2,%3}, {%4,%5,%6,%7}, {%8,%9}, {%0,%1,%2,%3};"
        : "+f"(c.x), "+f"(c.y), "+f"(c.z), "+f"(c.w)
        : "r"(a[0]), "r"(a[1]), "r"(a[2]), "r"(a[3]), "r"(b0), "r"(b1));
}
__device__ __forceinline__ unsigned sptr(const void* p) {
    return (unsigned)__cvta_generic_to_shared(p);
}
__device__ __forceinline__ void cpa16(unsigned dst, const void* src) {
    asm volatile("cp.async.cg.shared.global [%0], [%1], 16;" :: "r"(dst), "l"(src));
}
#define CP_COMMIT() asm volatile("cp.async.commit_group;")
#define CP_WAIT(n)  asm volatile("cp.async.wait_group %0;" :: "n"(n))

// ---------------------------------------------------------------------------
// Kernel 1: rp table
// ---------------------------------------------------------------------------
__global__ void rp_kernel(const float* __restrict__ h_pos,
                          const float* __restrict__ w_pos) {
    int i = blockIdx.x * blockDim.x + threadIdx.x;
    if (i >= CDIM * NPIX) return;
    int m = i & (NPIX - 1);
    int c = i >> 10;
    g_rp[i] = h_pos[(m >> 5) * CDIM + c] + w_pos[(m & 31) * CDIM + c];
}

// ---------------------------------------------------------------------------
// Prep kernels (one-time split into interleaved hi/lo)
// ---------------------------------------------------------------------------
__global__ void prep_w(const float* __restrict__ wmat) {
    int i = blockIdx.x * blockDim.x + threadIdx.x;
    if (i >= OC * 64) return;
    int o  = i >> 6;
    int c8 = (i & 63) * 8;
    float4 a = *(const float4*)&wmat[o * CDIM + c8];
    float4 b = *(const float4*)&wmat[o * CDIM + c8 + 4];
    uint4 u0, u1;
    split2(a.x, a.y, u0.x, u0.y); split2(a.z, a.w, u0.z, u0.w);
    split2(b.x, b.y, u1.x, u1.y); split2(b.z, b.w, u1.z, u1.w);
    ((uint4*)g_Whl)[2 * i]     = u0;
    ((uint4*)g_Whl)[2 * i + 1] = u1;
}

__global__ void prep_x(const float* __restrict__ x) {
    int i = blockIdx.x * blockDim.x + threadIdx.x;
    if (i >= BATCH * 256 * 256) return;
    int bj  = i >> 8;
    int hw4 = (i & 255) * 4;
    const float* r0 = &x[(bj * 2) * NPIX + hw4];
    float4 u = *(const float4*)r0;
    float4 v = *(const float4*)(r0 + NPIX);
    uint4 u0, u1;
    split2(u.x, v.x, u0.x, u0.y); split2(u.y, v.y, u0.z, u0.w);
    split2(u.z, v.z, u1.x, u1.y); split2(u.w, v.w, u1.z, u1.w);
    ((uint4*)g_Xhl)[2 * i]     = u0;
    ((uint4*)g_Xhl)[2 * i + 1] = u1;
}

// ---------------------------------------------------------------------------
// Kernel 2: QKV GEMM, bf16x3 mma, 4-stage cp.async pipeline (wait_group 2).
// 128(o) x 128(hw) tile, 8 warps (4M x 2N). Stage = k16 (8 kp).
// Smem (uint2): A [4][128][12]  B [4][8][132]
// ---------------------------------------------------------------------------
#define QA_ST (128 * 12)
#define QB_ST (8 * 132)

__global__ __launch_bounds__(256) void qkv_kernel() {
    extern __shared__ uint2 qsm[];
    uint2* Asm = qsm;                  // 4 stages
    uint2* Bsm = qsm + 4 * QA_ST;

    const int b   = blockIdx.z;
    const int oc0 = blockIdx.y * 128;
    const int hw0 = blockIdx.x * 128;
    const int tid = threadIdx.x;
    const int w   = tid >> 5, lane = tid & 31;
    const int g   = lane >> 2, tg = lane & 3;
    const int wm  = w & 3, wn = w >> 2;

    float4 acc[2][8];
#pragma unroll
    for (int i = 0; i < 2; i++)
#pragma unroll
        for (int j = 0; j < 8; j++) acc[i][j] = make_float4(0.f, 0.f, 0.f, 0.f);

    auto load_stage = [&](int st, int cp0) {
#pragma unroll
        for (int l = 0; l < 2; l++) {       // A: 512 chunks of 16B
            int ca = tid + l * 256;
            int r  = ca >> 2;
            int k2 = (ca & 3) * 2;
            cpa16(sptr(&Asm[st * QA_ST + r * 12 + k2]),
                  &g_Whl[(oc0 + r) * 256 + cp0 + k2]);
        }
#pragma unroll
        for (int l = 0; l < 2; l++) {       // B: 512 chunks
            int cb = tid + l * 256;
            int j  = cb >> 6;
            int n2 = (cb & 63) * 2;
            cpa16(sptr(&Bsm[st * QB_ST + j * 132 + n2]),
                  &g_Xhl[(b * 256 + cp0 + j) * NPIX + hw0 + n2]);
        }
        CP_COMMIT();
    };

    load_stage(0, 0);
    load_stage(1, 8);
    load_stage(2, 16);

    for (int s = 0; s < 32; s++) {
        CP_WAIT(2);
        __syncthreads();
        if (s + 3 < 32) load_stage((s + 3) & 3, (s + 3) * 8);
        else            CP_COMMIT();       // keep group count invariant

        const uint2* As = Asm + (s & 3) * QA_ST;
        const uint2* Bs = Bsm + (s & 3) * QB_ST;

        unsigned ah[2][4], al[2][4];
#pragma unroll
        for (int mt = 0; mt < 2; mt++) {
            int mr = wm * 32 + mt * 16 + g;
            uint2 a0 = As[mr * 12 + tg];
            uint2 a1 = As[(mr + 8) * 12 + tg];
            uint2 a2 = As[mr * 12 + tg + 4];
            uint2 a3 = As[(mr + 8) * 12 + tg + 4];
            ah[mt][0] = a0.x; al[mt][0] = a0.y;
            ah[mt][1] = a1.x; al[mt][1] = a1.y;
            ah[mt][2] = a2.x; al[mt][2] = a2.y;
            ah[mt][3] = a3.x; al[mt][3] = a3.y;
        }
#pragma unroll
        for (int nt = 0; nt < 8; nt++) {
            int n = wn * 64 + nt * 8 + g;
            uint2 u0 = Bs[tg * 132 + n];
            uint2 u1 = Bs[(tg + 4) * 132 + n];
#pragma unroll
            for (int mt = 0; mt < 2; mt++) {
                mma16(acc[mt][nt], ah[mt], u0.x, u1.x);
                mma16(acc[mt][nt], ah[mt], u0.y, u1.y);
                mma16(acc[mt][nt], al[mt], u0.x, u1.x);
            }
        }
    }

    // Epilogue: which 0=Q, 1=K(+rp), 2=V(fp16, kp-permuted)
    const int which = oc0 >> 9;

#pragma unroll
    for (int mt = 0; mt < 2; mt++)
#pragma unroll
        for (int half = 0; half < 2; half++) {
            int o  = oc0 + wm * 32 + mt * 16 + g + half * 8;
            int oo = o & 511;
#pragma unroll
            for (int nt = 0; nt < 8; nt++) {
                int hw = hw0 + wn * 64 + nt * 8 + 2 * tg;
                float2 v = half ? make_float2(acc[mt][nt].z, acc[mt][nt].w)
                                : make_float2(acc[mt][nt].x, acc[mt][nt].y);
                if (which == 2) {
                    int kp  = hw >> 1;
                    int kpp = (kp & ~7) | ((kp & 3) << 1) | ((kp >> 2) & 1);
                    g_Vh[(b * 512 + oo) * 512 + kpp] = packh2(v.x, v.y);
                } else {
                    if (which == 1) {
                        float2 r = *(const float2*)&g_rp[oo * NPIX + hw];
                        v.x += r.x; v.y += r.y;
                    }
                    float px = __shfl_xor_sync(0xffffffffu, v.x, 4);
                    float py = __shfl_xor_sync(0xffffffffu, v.y, 4);
                    if (!(g & 1)) {
                        uint4 u;
                        split2(v.x, px, u.x, u.y);
                        split2(v.y, py, u.z, u.w);
                        uint2* dhl = which ? g_Khl : g_Qhl;
                        int base = (b * 256 + (oo >> 1)) * NPIX + hw;
                        *(uint4*)&dhl[base] = u;
                    }
                }
            }
        }
}

// ---------------------------------------------------------------------------
// Kernel 3: flash attention, double-buffered cp.async tiles.
// S = QK'^T bf16x3 (hi/lo interleaved K), PV fp16 (V kp-permuted).
// Stage (bytes): K 32*132*8 = 33792 | V 64*72*4 = 18432  -> 52224
// ---------------------------------------------------------------------------
#define AK_ST (32 * 132)      // uint2
#define AV_ST (64 * 72)       // uint

__global__ __launch_bounds__(256) void attn_kernel(float* __restrict__ out) {
    extern __shared__ uint2 asm2[];
    uint2*    Kb = asm2;                        // 2 stages of K
    unsigned* Vb = (unsigned*)(asm2 + 2 * AK_ST);

    const int b = blockIdx.z, p = blockIdx.y;
    const int tid  = threadIdx.x;
    const int w    = tid >> 5, lane = tid & 31;
    const int g    = lane >> 2, tg = lane & 3;
    const int q0   = blockIdx.x * 128;
    const int bp32 = b * 256 + p * 32;
    const int vb   = b * 512 + p * 64;

    auto load_tile = [&](int st, int kv) {
        uint2*    Ks = Kb + st * AK_ST;
        unsigned* Vs = Vb + st * AV_ST;
#pragma unroll
        for (int t = 0; t < 8; t++) {           // K: 2048 16B chunks
            int i  = tid + t * 256;
            int dp = i >> 6;
            int c  = (i & 63) * 2;
            cpa16(sptr(&Ks[dp * 132 + c]), &g_Khl[(bp32 + dp) * NPIX + kv + c]);
        }
#pragma unroll
        for (int t = 0; t < 4; t++) {           // V: 1024 16B chunks
            int i  = tid + t * 256;
            int d  = i >> 4;
            int c4 = (i & 15) * 4;
            cpa16(sptr(&Vs[d * 72 + c4]), &g_Vh[(vb + d) * 512 + (kv >> 1) + c4]);
        }
        CP_COMMIT();
    };

    // Q A-fragments from interleaved global
    unsigned qh[4][4], ql[4][4];
    {
        int qr = q0 + w * 16 + g;
#pragma unroll
        for (int kt = 0; kt < 4; kt++)
#pragma unroll
            for (int r = 0; r < 4; r++) {
                int row = qr + ((r & 1) ? 8 : 0);
                int dp  = kt * 8 + tg + ((r & 2) ? 4 : 0);
                uint2 q = g_Qhl[(bp32 + dp) * NPIX + row];
                qh[kt][r] = q.x; ql[kt][r] = q.y;
            }
    }

    float4 oacc[8];
#pragma unroll
    for (int i = 0; i < 8; i++) oacc[i] = make_float4(0.f, 0.f, 0.f, 0.f);
    float mr0 = -1e30f, mr1 = -1e30f, lr0 = 0.f, lr1 = 0.f;

    load_tile(0, 0);

    for (int s = 0; s < 8; s++) {
        CP_WAIT(0);
        __syncthreads();
        if (s < 7) load_tile((s + 1) & 1, (s + 1) * 128);

        const uint2*    Ks = Kb + (s & 1) * AK_ST;
        const unsigned* Vs = Vb + (s & 1) * AV_ST;

        // S = Q K'^T, bf16x3
        float4 sacc[16];
#pragma unroll
        for (int i = 0; i < 16; i++) sacc[i] = make_float4(0.f, 0.f, 0.f, 0.f);
#pragma unroll
        for (int kt = 0; kt < 4; kt++) {
#pragma unroll
            for (int nt = 0; nt < 16; nt++) {
                int n = nt * 8 + g;
                uint2 u0 = Ks[(kt * 8 + tg) * 132 + n];
                uint2 u1 = Ks[(kt * 8 + tg + 4) * 132 + n];
                mma16(sacc[nt], qh[kt], u0.x, u1.x);
                mma16(sacc[nt], qh[kt], u0.y, u1.y);
                mma16(sacc[nt], ql[kt], u0.x, u1.x);
            }
        }

        // Online softmax (rows g, g+8)
        float rm0 = -1e30f, rm1 = -1e30f;
#pragma unroll
        for (int nt = 0; nt < 16; nt++) {
            rm0 = fmaxf(rm0, fmaxf(sacc[nt].x, sacc[nt].y));
            rm1 = fmaxf(rm1, fmaxf(sacc[nt].z, sacc[nt].w));
        }
        rm0 = fmaxf(rm0, __shfl_xor_sync(0xffffffffu, rm0, 1));
        rm0 = fmaxf(rm0, __shfl_xor_sync(0xffffffffu, rm0, 2));
        rm1 = fmaxf(rm1, __shfl_xor_sync(0xffffffffu, rm1, 1));
        rm1 = fmaxf(rm1, __shfl_xor_sync(0xffffffffu, rm1, 2));
        float nm0 = fmaxf(mr0, rm0), nm1 = fmaxf(mr1, rm1);
        float cr0 = __expf(mr0 - nm0), cr1 = __expf(mr1 - nm1);
        mr0 = nm0; mr1 = nm1;

        float s0 = 0.f, s1 = 0.f;
#pragma unroll
        for (int nt = 0; nt < 16; nt++) {
            sacc[nt].x = __expf(sacc[nt].x - nm0);
            sacc[nt].y = __expf(sacc[nt].y - nm0);
            sacc[nt].z = __expf(sacc[nt].z - nm1);
            sacc[nt].w = __expf(sacc[nt].w - nm1);
            s0 += sacc[nt].x + sacc[nt].y;
            s1 += sacc[nt].z + sacc[nt].w;
        }
        s0 += __shfl_xor_sync(0xffffffffu, s0, 1);
        s0 += __shfl_xor_sync(0xffffffffu, s0, 2);
        s1 += __shfl_xor_sync(0xffffffffu, s1, 1);
        s1 += __shfl_xor_sync(0xffffffffu, s1, 2);
        lr0 = lr0 * cr0 + s0;
        lr1 = lr1 * cr1 + s1;
#pragma unroll
        for (int nt = 0; nt < 8; nt++) {
            oacc[nt].x *= cr0; oacc[nt].y *= cr0;
            oacc[nt].z *= cr1; oacc[nt].w *= cr1;
        }

        // O += P V : C-frag -> fp16 A-frag in registers; V pairs adjacent
#pragma unroll
        for (int kt = 0; kt < 8; kt++) {
            unsigned a[4];
            a[0] = packh2(sacc[2 * kt].x,     sacc[2 * kt].y);
            a[1] = packh2(sacc[2 * kt].z,     sacc[2 * kt].w);
            a[2] = packh2(sacc[2 * kt + 1].x, sacc[2 * kt + 1].y);
            a[3] = packh2(sacc[2 * kt + 1].z, sacc[2 * kt + 1].w);
#pragma unroll
            for (int nt = 0; nt < 8; nt++) {
                uint2 vv = *(const uint2*)&Vs[(nt * 8 + g) * 72 + kt * 8 + 2 * tg];
                mma16f(oacc[nt], a, vv.x, vv.y);
            }
        }
    }

    // Epilogue: normalize, transpose via smem overlay, coalesced store
    __syncthreads();
    float* Pw = (float*)asm2 + w * (16 * 68);
    float il0 = 1.f / lr0, il1 = 1.f / lr1;
#pragma unroll
    for (int nt = 0; nt < 8; nt++) {
        *(float2*)&Pw[g * 68 + nt * 8 + 2 * tg] =
            make_float2(oacc[nt].x * il0, oacc[nt].y * il0);
        *(float2*)&Pw[(g + 8) * 68 + nt * 8 + 2 * tg] =
            make_float2(oacc[nt].z * il1, oacc[nt].w * il1);
    }
    __syncwarp();
    int qbase = q0 + w * 16;
#pragma unroll
    for (int rep = 0; rep < 2; rep++) {
        int d = rep * 32 + lane;
        float vals[16];
#pragma unroll
        for (int r = 0; r < 16; r++) vals[r] = Pw[r * 68 + d];
        float* op = out + (b * CDIM + p * DH + d) * NPIX + qbase;
#pragma unroll
        for (int r4 = 0; r4 < 4; r4++)
            *(float4*)&op[r4 * 4] =
                make_float4(vals[r4 * 4], vals[r4 * 4 + 1], vals[r4 * 4 + 2], vals[r4 * 4 + 3]);
    }
}

// ---------------------------------------------------------------------------
extern "C" void kernel_launch(void* const* d_in, const int* in_sizes, int n_in,
                              void* d_out, int out_size) {
    const float* x     = (const float*)d_in[0];
    const float* qkv_w = (const float*)d_in[1];
    const float* h_pos = (const float*)d_in[2];
    const float* w_pos = (const float*)d_in[3];
    float* out = (float*)d_out;

    const int qkv_smem  = (4 * QA_ST + 4 * QB_ST) * (int)sizeof(uint2);          // 82944
    const int attn_smem = (2 * AK_ST) * (int)sizeof(uint2) + 2 * AV_ST * 4;      // 104448
    static int smem_set = 0;
    if (!smem_set) {
        cudaFuncSetAttribute(qkv_kernel,  cudaFuncAttributeMaxDynamicSharedMemorySize, qkv_smem);
        cudaFuncSetAttribute(attn_kernel, cudaFuncAttributeMaxDynamicSharedMemorySize, attn_smem);
        smem_set = 1;
    }

    rp_kernel<<<(CDIM * NPIX + 255) / 256, 256>>>(h_pos, w_pos);
    prep_w<<<(OC * 64 + 255) / 256, 256>>>(qkv_w);
    prep_x<<<(BATCH * 256 * 256 + 255) / 256, 256>>>(x);

    dim3 g2(NPIX / 128, OC / 128, BATCH);   // 8 x 12 x 32
    qkv_kernel<<<g2, 256, qkv_smem>>>();

    dim3 g3(NPIX / 128, HEADS, BATCH);      // 8 x 8 x 32
    attn_kernel<<<g3, 256, attn_smem>>>(out);
}

// round 14
// speedup vs baseline: 1.0767x; 1.0767x over previous
#include <cuda_runtime.h>
#include <cuda_bf16.h>
#include <cuda_fp16.h>

#define BATCH 32
#define CDIM  512
#define LSIZE 32
#define NPIX  1024
#define HEADS 8
#define DH    64
#define OC    1536

// ---------------------------------------------------------------------------
// Device scratch (round-10 proven layouts: separate hi/lo arrays)
// ---------------------------------------------------------------------------
__device__ float    g_rp[CDIM * NPIX];
__device__ unsigned g_Wh[OC * CDIM / 2];
__device__ unsigned g_Wl[OC * CDIM / 2];
__device__ unsigned g_Xh[BATCH * (CDIM / 2) * NPIX];
__device__ unsigned g_Xl[BATCH * (CDIM / 2) * NPIX];
__device__ unsigned g_Qh[BATCH * (CDIM / 2) * NPIX];
__device__ unsigned g_Ql[BATCH * (CDIM / 2) * NPIX];
__device__ unsigned g_Kh[BATCH * (CDIM / 2) * NPIX];
__device__ unsigned g_Kl[BATCH * (CDIM / 2) * NPIX];
__device__ unsigned g_Vh[BATCH * CDIM * (NPIX / 2)];

// ---------------------------------------------------------------------------
// helpers
// ---------------------------------------------------------------------------
__device__ __forceinline__ void split2(float x0, float x1, unsigned& h, unsigned& l) {
    __nv_bfloat16 h0 = __float2bfloat16(x0);
    __nv_bfloat16 h1 = __float2bfloat16(x1);
    __nv_bfloat16 l0 = __float2bfloat16(x0 - __bfloat162float(h0));
    __nv_bfloat16 l1 = __float2bfloat16(x1 - __bfloat162float(h1));
    h = ((unsigned)__bfloat16_as_ushort(h1) << 16) | __bfloat16_as_ushort(h0);
    l = ((unsigned)__bfloat16_as_ushort(l1) << 16) | __bfloat16_as_ushort(l0);
}
__device__ __forceinline__ unsigned packh2(float x0, float x1) {
    __half2 h = __floats2half2_rn(x0, x1);
    return *(unsigned*)&h;
}
__device__ __forceinline__ void mma16(float4& c, const unsigned* a, unsigned b0, unsigned b1) {
    asm volatile(
        "mma.sync.aligned.m16n8k16.row.col.f32.bf16.bf16.f32 "
        "{%0,%1,%2,%3}, {%4,%5,%6,%7}, {%8,%9}, {%0,%1,%2,%3};"
        : "+f"(c.x), "+f"(c.y), "+f"(c.z), "+f"(c.w)
        : "r"(a[0]), "r"(a[1]), "r"(a[2]), "r"(a[3]), "r"(b0), "r"(b1));
}
__device__ __forceinline__ void mma16f(float4& c, const unsigned* a, unsigned b0, unsigned b1) {
    asm volatile(
        "mma.sync.aligned.m16n8k16.row.col.f32.f16.f16.f32 "
        "{%0,%1,%2,%3}, {%4,%5,%6,%7}, {%8,%9}, {%0,%1,%2,%3};"
        : "+f"(c.x), "+f"(c.y), "+f"(c.z), "+f"(c.w)
        : "r"(a[0]), "r"(a[1]), "r"(a[2]), "r"(a[3]), "r"(b0), "r"(b1));
}
__device__ __forceinline__ unsigned sptr(const void* p) {
    return (unsigned)__cvta_generic_to_shared(p);
}
__device__ __forceinline__ void cpa16(unsigned dst, const void* src) {
    asm volatile("cp.async.cg.shared.global [%0], [%1], 16;" :: "r"(dst), "l"(src));
}
#define CP_COMMIT() asm volatile("cp.async.commit_group;")
#define CP_WAIT(n)  asm volatile("cp.async.wait_group %0;" :: "n"(n))

// ---------------------------------------------------------------------------
// Kernel 1: rp table
// ---------------------------------------------------------------------------
__global__ void rp_kernel(const float* __restrict__ h_pos,
                          const float* __restrict__ w_pos) {
    int i = blockIdx.x * blockDim.x + threadIdx.x;
    if (i >= CDIM * NPIX) return;
    int m = i & (NPIX - 1);
    int c = i >> 10;
    g_rp[i] = h_pos[(m >> 5) * CDIM + c] + w_pos[(m & 31) * CDIM + c];
}

// ---------------------------------------------------------------------------
// Prep kernels (one-time split)
// ---------------------------------------------------------------------------
__global__ void prep_w(const float* __restrict__ wmat) {
    int i = blockIdx.x * blockDim.x + threadIdx.x;
    if (i >= OC * 64) return;
    int o  = i >> 6;
    int c8 = (i & 63) * 8;
    float4 a = *(const float4*)&wmat[o * CDIM + c8];
    float4 b = *(const float4*)&wmat[o * CDIM + c8 + 4];
    uint4 H, L;
    split2(a.x, a.y, H.x, L.x); split2(a.z, a.w, H.y, L.y);
    split2(b.x, b.y, H.z, L.z); split2(b.z, b.w, H.w, L.w);
    ((uint4*)g_Wh)[i] = H;
    ((uint4*)g_Wl)[i] = L;
}

__global__ void prep_x(const float* __restrict__ x) {
    int i = blockIdx.x * blockDim.x + threadIdx.x;
    if (i >= BATCH * 256 * 256) return;
    int bj  = i >> 8;
    int hw4 = (i & 255) * 4;
    const float* r0 = &x[(bj * 2) * NPIX + hw4];
    float4 u = *(const float4*)r0;
    float4 v = *(const float4*)(r0 + NPIX);
    uint4 H, L;
    split2(u.x, v.x, H.x, L.x); split2(u.y, v.y, H.y, L.y);
    split2(u.z, v.z, H.z, L.z); split2(u.w, v.w, H.w, L.w);
    ((uint4*)g_Xh)[i] = H;
    ((uint4*)g_Xl)[i] = L;
}

// ---------------------------------------------------------------------------
// Kernel 2: QKV GEMM, bf16x3 mma, 4-stage cp.async pipeline (wait_group 2),
// stage indices compile-time via x4 loop unroll. Round-10 smem strides.
// Stage layout (uints): Ah[128*12] Al[128*12] Bh[8*136] Bl[8*136] = 5248
// ---------------------------------------------------------------------------
#define QST 5248

__global__ __launch_bounds__(256) void qkv_kernel() {
    extern __shared__ unsigned qsm[];

    const int b   = blockIdx.z;
    const int oc0 = blockIdx.y * 128;
    const int hw0 = blockIdx.x * 128;
    const int tid = threadIdx.x;
    const int w   = tid >> 5, lane = tid & 31;
    const int g   = lane >> 2, tg = lane & 3;
    const int wm  = w & 3, wn = w >> 2;

    float4 acc[2][8];
#pragma unroll
    for (int i = 0; i < 2; i++)
#pragma unroll
        for (int j = 0; j < 8; j++) acc[i][j] = make_float4(0.f, 0.f, 0.f, 0.f);

    const int ar  = tid >> 1;          // A row 0..127
    const int ak4 = (tid & 1) * 4;     // kp offset 0/4
    const int bj  = tid >> 5;          // B kp row 0..7
    const int bn4 = (tid & 31) * 4;

    auto load_stage = [&](int st, int cp0) {
        unsigned* Ah = qsm + st * QST;
        unsigned* Al = Ah + 1536;
        unsigned* Bh = Ah + 3072;
        unsigned* Bl = Ah + 4160;
        cpa16(sptr(&Ah[ar * 12 + ak4]),  &g_Wh[(oc0 + ar) * 256 + cp0 + ak4]);
        cpa16(sptr(&Al[ar * 12 + ak4]),  &g_Wl[(oc0 + ar) * 256 + cp0 + ak4]);
        cpa16(sptr(&Bh[bj * 136 + bn4]), &g_Xh[(b * 256 + cp0 + bj) * NPIX + hw0 + bn4]);
        cpa16(sptr(&Bl[bj * 136 + bn4]), &g_Xl[(b * 256 + cp0 + bj) * NPIX + hw0 + bn4]);
        CP_COMMIT();
    };

    load_stage(0, 0);
    load_stage(1, 8);
    load_stage(2, 16);

#pragma unroll 1
    for (int s0 = 0; s0 < 32; s0 += 4) {
#pragma unroll
        for (int u = 0; u < 4; u++) {          // u == stage index (compile-time)
            const int s = s0 + u;
            CP_WAIT(2);
            __syncthreads();
            if (s + 3 < 32) load_stage((u + 3) & 3, (s + 3) * 8);
            else            CP_COMMIT();

            const unsigned* Ah = qsm + u * QST;
            const unsigned* Al = Ah + 1536;
            const unsigned* Bh = Ah + 3072;
            const unsigned* Bl = Ah + 4160;

            unsigned ah[2][4], al[2][4];
#pragma unroll
            for (int mt = 0; mt < 2; mt++) {
                int mr = wm * 32 + mt * 16 + g;
                ah[mt][0] = Ah[mr * 12 + tg];           al[mt][0] = Al[mr * 12 + tg];
                ah[mt][1] = Ah[(mr + 8) * 12 + tg];     al[mt][1] = Al[(mr + 8) * 12 + tg];
                ah[mt][2] = Ah[mr * 12 + tg + 4];       al[mt][2] = Al[mr * 12 + tg + 4];
                ah[mt][3] = Ah[(mr + 8) * 12 + tg + 4]; al[mt][3] = Al[(mr + 8) * 12 + tg + 4];
            }
#pragma unroll
            for (int nt = 0; nt < 8; nt++) {
                int n = wn * 64 + nt * 8 + g;
                unsigned bh0 = Bh[tg * 136 + n], bh1 = Bh[(tg + 4) * 136 + n];
                unsigned bl0 = Bl[tg * 136 + n], bl1 = Bl[(tg + 4) * 136 + n];
#pragma unroll
                for (int mt = 0; mt < 2; mt++) {
                    mma16(acc[mt][nt], ah[mt], bh0, bh1);
                    mma16(acc[mt][nt], ah[mt], bl0, bl1);
                    mma16(acc[mt][nt], al[mt], bh0, bh1);
                }
            }
        }
    }

    // Epilogue: which 0=Q, 1=K(+rp), 2=V. (round-10)
    const int which = oc0 >> 9;

#pragma unroll
    for (int mt = 0; mt < 2; mt++)
#pragma unroll
        for (int half = 0; half < 2; half++) {
            int o  = oc0 + wm * 32 + mt * 16 + g + half * 8;
            int oo = o & 511;
#pragma unroll
            for (int nt = 0; nt < 8; nt++) {
                int hw = hw0 + wn * 64 + nt * 8 + 2 * tg;
                float2 v = half ? make_float2(acc[mt][nt].z, acc[mt][nt].w)
                                : make_float2(acc[mt][nt].x, acc[mt][nt].y);
                if (which == 2) {
                    g_Vh[(b * 512 + oo) * 512 + (hw >> 1)] = packh2(v.x, v.y);
                } else {
                    if (which == 1) {
                        float2 r = *(const float2*)&g_rp[oo * NPIX + hw];
                        v.x += r.x; v.y += r.y;
                    }
                    float px = __shfl_xor_sync(0xffffffffu, v.x, 4);
                    float py = __shfl_xor_sync(0xffffffffu, v.y, 4);
                    if (!(g & 1)) {
                        unsigned h0, l0, h1, l1;
                        split2(v.x, px, h0, l0);
                        split2(v.y, py, h1, l1);
                        unsigned* dh = which ? g_Kh : g_Qh;
                        unsigned* dl = which ? g_Kl : g_Ql;
                        int base = (b * 256 + (oo >> 1)) * NPIX + hw;
                        *(uint2*)&dh[base] = make_uint2(h0, h1);
                        *(uint2*)&dl[base] = make_uint2(l0, l1);
                    }
                }
            }
        }
}

// ---------------------------------------------------------------------------
// Kernel 3: flash attention (round-10, 2-stage cp.async double buffer).
// Stage layout (words): Kh[32][136] | Kl[32][136] | Vh[64][68]  = 13056
// ---------------------------------------------------------------------------
#define AST 13056

__global__ __launch_bounds__(256) void attn_kernel(float* __restrict__ out) {
    extern __shared__ unsigned smu[];

    const int b = blockIdx.z, p = blockIdx.y;
    const int tid  = threadIdx.x;
    const int w    = tid >> 5, lane = tid & 31;
    const int g    = lane >> 2, tg = lane & 3;
    const int q0   = blockIdx.x * 128;
    const int bp32 = b * 256 + p * 32;
    const int vb   = b * 512 + p * 64;

    auto load_tile = [&](int st, int kv) {
        unsigned* Khs = smu + st * AST;
        unsigned* Kls = Khs + 32 * 136;
        unsigned* Vhs = Kls + 32 * 136;
#pragma unroll
        for (int t = 0; t < 4; t++) {
            int i  = tid + t * 256;
            int dp = i >> 5;
            int k4 = (i & 31) * 4;
            cpa16(sptr(&Khs[dp * 136 + k4]), &g_Kh[(bp32 + dp) * NPIX + kv + k4]);
            cpa16(sptr(&Kls[dp * 136 + k4]), &g_Kl[(bp32 + dp) * NPIX + kv + k4]);
        }
#pragma unroll
        for (int t = 0; t < 4; t++) {
            int i   = tid + t * 256;
            int d   = i >> 4;
            int kp4 = (i & 15) * 4;
            cpa16(sptr(&Vhs[d * 68 + kp4]), &g_Vh[(vb + d) * 512 + (kv >> 1) + kp4]);
        }
        CP_COMMIT();
    };

    unsigned qh[4][4], ql[4][4];
    {
        int qr = q0 + w * 16 + g;
#pragma unroll
        for (int kt = 0; kt < 4; kt++)
#pragma unroll
            for (int r = 0; r < 4; r++) {
                int row = qr + ((r & 1) ? 8 : 0);
                int dp  = kt * 8 + tg + ((r & 2) ? 4 : 0);
                qh[kt][r] = g_Qh[(bp32 + dp) * NPIX + row];
                ql[kt][r] = g_Ql[(bp32 + dp) * NPIX + row];
            }
    }

    float4 oacc[8];
#pragma unroll
    for (int i = 0; i < 8; i++) oacc[i] = make_float4(0.f, 0.f, 0.f, 0.f);
    float mr0 = -1e30f, mr1 = -1e30f, lr0 = 0.f, lr1 = 0.f;

    load_tile(0, 0);

    for (int s = 0; s < 8; s++) {
        CP_WAIT(0);
        __syncthreads();
        if (s < 7) load_tile((s + 1) & 1, (s + 1) * 128);

        unsigned* Khs = smu + (s & 1) * AST;
        unsigned* Kls = Khs + 32 * 136;
        unsigned* Vhs = Kls + 32 * 136;

        float4 sacc[16];
#pragma unroll
        for (int i = 0; i < 16; i++) sacc[i] = make_float4(0.f, 0.f, 0.f, 0.f);
#pragma unroll
        for (int kt = 0; kt < 4; kt++) {
#pragma unroll
            for (int nt = 0; nt < 16; nt++) {
                int n = nt * 8 + g;
                unsigned bh0 = Khs[(kt * 8 + tg) * 136 + n];
                unsigned bh1 = Khs[(kt * 8 + tg + 4) * 136 + n];
                unsigned bl0 = Kls[(kt * 8 + tg) * 136 + n];
                unsigned bl1 = Kls[(kt * 8 + tg + 4) * 136 + n];
                mma16(sacc[nt], qh[kt], bh0, bh1);
                mma16(sacc[nt], qh[kt], bl0, bl1);
                mma16(sacc[nt], ql[kt], bh0, bh1);
            }
        }

        float rm0 = -1e30f, rm1 = -1e30f;
#pragma unroll
        for (int nt = 0; nt < 16; nt++) {
            rm0 = fmaxf(rm0, fmaxf(sacc[nt].x, sacc[nt].y));
            rm1 = fmaxf(rm1, fmaxf(sacc[nt].z, sacc[nt].w));
        }
        rm0 = fmaxf(rm0, __shfl_xor_sync(0xffffffffu, rm0, 1));
        rm0 = fmaxf(rm0, __shfl_xor_sync(0xffffffffu, rm0, 2));
        rm1 = fmaxf(rm1, __shfl_xor_sync(0xffffffffu, rm1, 1));
        rm1 = fmaxf(rm1, __shfl_xor_sync(0xffffffffu, rm1, 2));
        float nm0 = fmaxf(mr0, rm0), nm1 = fmaxf(mr1, rm1);
        float cr0 = __expf(mr0 - nm0), cr1 = __expf(mr1 - nm1);
        mr0 = nm0; mr1 = nm1;

        float s0 = 0.f, s1 = 0.f;
#pragma unroll
        for (int nt = 0; nt < 16; nt++) {
            sacc[nt].x = __expf(sacc[nt].x - nm0);
            sacc[nt].y = __expf(sacc[nt].y - nm0);
            sacc[nt].z = __expf(sacc[nt].z - nm1);
            sacc[nt].w = __expf(sacc[nt].w - nm1);
            s0 += sacc[nt].x + sacc[nt].y;
            s1 += sacc[nt].z + sacc[nt].w;
        }
        s0 += __shfl_xor_sync(0xffffffffu, s0, 1);
        s0 += __shfl_xor_sync(0xffffffffu, s0, 2);
        s1 += __shfl_xor_sync(0xffffffffu, s1, 1);
        s1 += __shfl_xor_sync(0xffffffffu, s1, 2);
        lr0 = lr0 * cr0 + s0;
        lr1 = lr1 * cr1 + s1;
#pragma unroll
        for (int nt = 0; nt < 8; nt++) {
            oacc[nt].x *= cr0; oacc[nt].y *= cr0;
            oacc[nt].z *= cr1; oacc[nt].w *= cr1;
        }

#pragma unroll
        for (int kt = 0; kt < 8; kt++) {
            unsigned a[4];
            a[0] = packh2(sacc[2 * kt].x,     sacc[2 * kt].y);
            a[1] = packh2(sacc[2 * kt].z,     sacc[2 * kt].w);
            a[2] = packh2(sacc[2 * kt + 1].x, sacc[2 * kt + 1].y);
            a[3] = packh2(sacc[2 * kt + 1].z, sacc[2 * kt + 1].w);
#pragma unroll
            for (int nt = 0; nt < 8; nt++) {
                unsigned b0 = Vhs[(nt * 8 + g) * 68 + kt * 8 + tg];
                unsigned b1 = Vhs[(nt * 8 + g) * 68 + kt * 8 + tg + 4];
                mma16f(oacc[nt], a, b0, b1);
            }
        }
    }

    __syncthreads();
    float* Pw = (float*)smu + w * (16 * 68);
    float il0 = 1.f / lr0, il1 = 1.f / lr1;
#pragma unroll
    for (int nt = 0; nt < 8; nt++) {
        *(float2*)&Pw[g * 68 + nt * 8 + 2 * tg] =
            make_float2(oacc[nt].x * il0, oacc[nt].y * il0);
        *(float2*)&Pw[(g + 8) * 68 + nt * 8 + 2 * tg] =
            make_float2(oacc[nt].z * il1, oacc[nt].w * il1);
    }
    __syncwarp();
    int qbase = q0 + w * 16;
#pragma unroll
    for (int rep = 0; rep < 2; rep++) {
        int d = rep * 32 + lane;
        float vals[16];
#pragma unroll
        for (int r = 0; r < 16; r++) vals[r] = Pw[r * 68 + d];
        float* op = out + (b * CDIM + p * DH + d) * NPIX + qbase;
#pragma unroll
        for (int r4 = 0; r4 < 4; r4++)
            *(float4*)&op[r4 * 4] =
                make_float4(vals[r4 * 4], vals[r4 * 4 + 1], vals[r4 * 4 + 2], vals[r4 * 4 + 3]);
    }
}

// ---------------------------------------------------------------------------
extern "C" void kernel_launch(void* const* d_in, const int* in_sizes, int n_in,
                              void* d_out, int out_size) {
    const float* x     = (const float*)d_in[0];
    const float* qkv_w = (const float*)d_in[1];
    const float* h_pos = (const float*)d_in[2];
    const float* w_pos = (const float*)d_in[3];
    float* out = (float*)d_out;

    const int qkv_smem  = 4 * QST * (int)sizeof(unsigned);   // 83968
    const int attn_smem = 2 * AST * (int)sizeof(unsigned);   // 104448
    static int smem_set = 0;
    if (!smem_set) {
        cudaFuncSetAttribute(qkv_kernel,  cudaFuncAttributeMaxDynamicSharedMemorySize, qkv_smem);
        cudaFuncSetAttribute(attn_kernel, cudaFuncAttributeMaxDynamicSharedMemorySize, attn_smem);
        smem_set = 1;
    }

    rp_kernel<<<(CDIM * NPIX + 255) / 256, 256>>>(h_pos, w_pos);
    prep_w<<<(OC * 64 + 255) / 256, 256>>>(qkv_w);
    prep_x<<<(BATCH * 256 * 256 + 255) / 256, 256>>>(x);

    dim3 g2(NPIX / 128, OC / 128, BATCH);   // 8 x 12 x 32
    qkv_kernel<<<g2, 256, qkv_smem>>>();

    dim3 g3(NPIX / 128, HEADS, BATCH);      // 8 x 8 x 32
    attn_kernel<<<g3, 256, attn_smem>>>(out);
}